// round 12
// baseline (speedup 1.0000x reference)
#include <cuda_runtime.h>
#include <cstdint>

#define HDIM 2048
#define MTOT 16384
#define COMBINED_ELEMS (MTOT * HDIM)
#define W_ELEMS (HDIM * HDIM)

// Scratch (static __device__ — no allocation allowed)
__device__ __align__(256) uint32_t g_xtf[MTOT * HDIM];    // x tf32, [m][h]
__device__ __align__(256) uint32_t g_xtfT[HDIM * MTOT];   // x tf32, [h][m]
__device__ __align__(256) uint32_t g_wtf[W_ELEMS];        // fixed+plastic tf32, [n][k]
__device__ __align__(256) uint32_t g_ctfT[HDIM * MTOT];   // combined tf32, [n][m]
__device__ float g_sumsq;

// ---------------------------------------------------------------------------
// Helpers (baseline sm_80+ ISA only)
// ---------------------------------------------------------------------------
__device__ __forceinline__ uint32_t f2tf32(float f) {
    uint32_t r;
    asm("cvt.rna.tf32.f32 %0, %1;" : "=r"(r) : "f"(f));
    return r;
}

__device__ __forceinline__ void mma_tf32(float* d, const uint32_t* a, const uint32_t* b) {
    asm volatile(
        "mma.sync.aligned.m16n8k8.row.col.f32.tf32.tf32.f32 "
        "{%0,%1,%2,%3}, {%4,%5,%6,%7}, {%8,%9}, {%0,%1,%2,%3};"
        : "+f"(d[0]), "+f"(d[1]), "+f"(d[2]), "+f"(d[3])
        : "r"(a[0]), "r"(a[1]), "r"(a[2]), "r"(a[3]), "r"(b[0]), "r"(b[1]));
}

#define LDSM_X4(d, addr) \
    asm volatile("ldmatrix.sync.aligned.m8n8.x4.shared.b16 {%0,%1,%2,%3}, [%4];" \
        : "=r"((d)[0]), "=r"((d)[1]), "=r"((d)[2]), "=r"((d)[3]) : "r"(addr))

__device__ __forceinline__ void cp16(uint32_t smem_addr, const void* gptr) {
    asm volatile("cp.async.cg.shared.global [%0], [%1], 16;"
                 :: "r"(smem_addr), "l"(gptr) : "memory");
}
__device__ __forceinline__ void cp_commit() {
    asm volatile("cp.async.commit_group;" ::: "memory");
}
__device__ __forceinline__ void cp_wait1() {
    asm volatile("cp.async.wait_group 1;" ::: "memory");
}
__device__ __forceinline__ void cp_wait0() {
    asm volatile("cp.async.wait_group 0;" ::: "memory");
}

// ---------------------------------------------------------------------------
// Small kernels
// ---------------------------------------------------------------------------
// g_wtf = tf32(fixed + plastic); also zero the norm accumulator
__global__ void wsumtf_kernel(const float* __restrict__ fw,
                              const float* __restrict__ pw) {
    if (blockIdx.x == 0 && threadIdx.x == 0) g_sumsq = 0.0f;
    int i = (blockIdx.x * blockDim.x + threadIdx.x) * 4;
    float4 a = *reinterpret_cast<const float4*>(&fw[i]);
    float4 b = *reinterpret_cast<const float4*>(&pw[i]);
    *reinterpret_cast<uint4*>(&g_wtf[i]) =
        make_uint4(f2tf32(a.x + b.x), f2tf32(a.y + b.y),
                   f2tf32(a.z + b.z), f2tf32(a.w + b.w));
}

// Fused: read x once, write g_xtf [m][h] (straight) and g_xtfT [h][m] (transposed)
__global__ void xcvt_kernel(const float* __restrict__ X) {
    __shared__ uint32_t t[32][33];
    int bx = blockIdx.x * 32;   // h
    int by = blockIdx.y * 32;   // m
    int tx = threadIdx.x, ty = threadIdx.y;
    #pragma unroll
    for (int j = 0; j < 32; j += 8) {
        uint32_t v = f2tf32(X[(size_t)(by + ty + j) * HDIM + bx + tx]);
        t[ty + j][tx] = v;
        g_xtf[(size_t)(by + ty + j) * HDIM + bx + tx] = v;
    }
    __syncthreads();
    #pragma unroll
    for (int j = 0; j < 32; j += 8)
        g_xtfT[(size_t)(bx + ty + j) * MTOT + by + tx] = t[tx][ty + j];
}

__global__ void scale_w_kernel(float* __restrict__ W) {
    float n = sqrtf(g_sumsq);
    float s = (n > 1.0f) ? (1.0f / n) : 1.0f;
    int i = (blockIdx.x * blockDim.x + threadIdx.x) * 4;
    float4 v = *reinterpret_cast<float4*>(&W[i]);
    v.x *= s; v.y *= s; v.z *= s; v.w *= s;
    *reinterpret_cast<float4*>(&W[i]) = v;
}

// ---------------------------------------------------------------------------
// Shared GEMM config: NT, 128(m) x 256(n) CTA tile, 512 threads, KCH=32,
// 3-stage cp.async, LDSM fragments.
// SMEM [row][k], row stride 36 u32 (LDSM 8-row phases conflict-free).
// 16 warps = 4(m) x 4(n), warp tile 32x64.  Occupancy: 1 CTA/SM (16 warps).
// ---------------------------------------------------------------------------
#define MT 128
#define NT 256
#define KCH 32
#define S1 36
#define A_MAT (MT * S1)                 // 4608 u32
#define B_MAT (NT * S1)                 // 9216 u32
#define G_STAGE (A_MAT + B_MAT)         // 13824 u32 = 55296 B
#define G_SMEM_BYTES (3 * G_STAGE * 4)  // 165888 B
#define EPI_STRIDE 132                  // transpose-staging stride

__device__ __forceinline__ void gemm_mainloop(
    const uint32_t* __restrict__ Aq, const uint32_t* __restrict__ Bq,
    int K, int r0g, int c0g,
    uint32_t shb,
    float acc[2][8][4])
{
    const int tid = threadIdx.x;
    const int lid = tid & 31;
    const int wid = tid >> 5;
    const int wm = wid & 3;
    const int wn = wid >> 2;          // 0..3
    const int nchunk = K / KCH;

    // LDSM per-lane byte offsets (within a stage's A / B matrix region)
    const uint32_t aoff0 =
        (uint32_t)((wm * 32 + ((lid >> 3) & 1) * 8 + (lid & 7)) * S1
                   + ((lid >> 4) & 1) * 4) * 4;
    const uint32_t aoff1 = aoff0 + 16 * S1 * 4;
    const uint32_t boff0 =
        (uint32_t)((wn * 64 + ((lid >> 4) & 1) * 8 + (lid & 7)) * S1
                   + ((lid >> 3) & 1) * 4) * 4;

    // cp.async staging: slot = tid + 512*i; row = slot>>3, kq = slot&7
    const int srow = tid >> 3;        // 0..63
    const int skq  = tid & 7;

    auto issue = [&](int c) {
        const int s = c % 3;
        const uint32_t sa = shb + (uint32_t)(s * G_STAGE) * 4;
        const uint32_t sb = sa + (uint32_t)A_MAT * 4;
        const int k0 = c * KCH;
        #pragma unroll
        for (int i = 0; i < 2; i++) {          // A: 128 rows
            int row = srow + i * 64;
            cp16(sa + (uint32_t)(row * S1 + skq * 4) * 4,
                 &Aq[(size_t)(r0g + row) * K + k0 + skq * 4]);
        }
        #pragma unroll
        for (int i = 0; i < 4; i++) {          // B: 256 rows
            int row = srow + i * 64;
            cp16(sb + (uint32_t)(row * S1 + skq * 4) * 4,
                 &Bq[(size_t)(c0g + row) * K + k0 + skq * 4]);
        }
        cp_commit();
    };

    issue(0);
    issue(1);

    for (int c = 0; c < nchunk; c++) {
        if (c >= nchunk - 2) cp_wait0(); else cp_wait1();
        __syncthreads();
        if (c + 2 < nchunk) issue(c + 2);

        const uint32_t sa = shb + (uint32_t)((c % 3) * G_STAGE) * 4;
        const uint32_t sb = sa + (uint32_t)A_MAT * 4;

        uint32_t afr[2][8];
        uint32_t bfr[2][4];
        LDSM_X4(&afr[0][0], sa + aoff0);
        LDSM_X4(&afr[0][4], sa + aoff1);
        LDSM_X4(bfr[0], sb + boff0);

        #pragma unroll
        for (int ks = 0; ks < 4; ks++) {
            const int ap = ks & 1;
            #pragma unroll
            for (int tp = 0; tp < 4; tp++) {
                if (tp < 3) {
                    LDSM_X4(bfr[(tp + 1) & 1],
                            sb + boff0 + (uint32_t)((tp + 1) * 16 * S1 * 4) + ks * 32);
                } else if (ks < 3) {
                    LDSM_X4(&afr[ap ^ 1][0], sa + aoff0 + (ks + 1) * 32);
                    LDSM_X4(&afr[ap ^ 1][4], sa + aoff1 + (ks + 1) * 32);
                    LDSM_X4(bfr[0], sb + boff0 + (ks + 1) * 32);
                }
                const uint32_t* bb = bfr[tp & 1];
                mma_tf32(acc[0][2 * tp],     &afr[ap][0], &bb[0]);
                mma_tf32(acc[1][2 * tp],     &afr[ap][4], &bb[0]);
                mma_tf32(acc[0][2 * tp + 1], &afr[ap][0], &bb[2]);
                mma_tf32(acc[1][2 * tp + 1], &afr[ap][4], &bb[2]);
            }
        }
    }
    __syncthreads();   // all compute done before smem reuse by caller
}

// ---------------------------------------------------------------------------
// GEMM1: C[m,n] = sum_k x[m,k]*wsum[n,k] + bias[n]
//   outputs: combined (fp32, [m][n]) and g_ctfT (tf32, [n][m])
// ---------------------------------------------------------------------------
__global__ __launch_bounds__(512, 1)
void gemm1_mma(const float* __restrict__ bias,
               float* __restrict__ C) {
    extern __shared__ uint32_t sh[];
    const uint32_t shb = (uint32_t)__cvta_generic_to_shared(sh);

    const int tid = threadIdx.x;
    const int wid = tid >> 5;
    const int lid = tid & 31;
    const int wm = wid & 3;
    const int wn = wid >> 2;
    const int r = lid >> 2;
    const int cq = lid & 3;
    const int m0 = blockIdx.y * MT;
    const int n0 = blockIdx.x * NT;

    float acc[2][8][4];
    #pragma unroll
    for (int i = 0; i < 2; i++)
        #pragma unroll
        for (int t = 0; t < 8; t++)
            #pragma unroll
            for (int q = 0; q < 4; q++) acc[i][t][q] = 0.0f;

    gemm_mainloop(g_xtf, g_wtf, HDIM, m0, n0, shb, acc);

    // direct fp32 write + transpose-stage tf32 into smem
    #pragma unroll
    for (int i = 0; i < 2; i++) {
        int rl = wm * 32 + 16 * i + r;
        #pragma unroll
        for (int t = 0; t < 8; t++) {
            int cl = wn * 64 + 8 * t + 2 * cq;
            float2 bv = *reinterpret_cast<const float2*>(&bias[n0 + cl]);
            float o0 = acc[i][t][0] + bv.x, o1 = acc[i][t][1] + bv.y;
            float o2 = acc[i][t][2] + bv.x, o3 = acc[i][t][3] + bv.y;
            size_t b0 = (size_t)(m0 + rl) * HDIM + n0 + cl;
            size_t b1 = (size_t)(m0 + rl + 8) * HDIM + n0 + cl;
            *reinterpret_cast<float2*>(&C[b0]) = make_float2(o0, o1);
            *reinterpret_cast<float2*>(&C[b1]) = make_float2(o2, o3);
            sh[cl * EPI_STRIDE + rl]           = f2tf32(o0);
            sh[(cl + 1) * EPI_STRIDE + rl]     = f2tf32(o1);
            sh[cl * EPI_STRIDE + rl + 8]       = f2tf32(o2);
            sh[(cl + 1) * EPI_STRIDE + rl + 8] = f2tf32(o3);
        }
    }
    __syncthreads();
    // coalesced store of transposed tile to g_ctfT: 256 cols x 32 m-quads
    #pragma unroll
    for (int it = 0; it < 16; it++) {
        int slot = tid + (it << 9);
        int col = slot >> 5, mq = slot & 31;
        uint4 v = *reinterpret_cast<const uint4*>(&sh[col * EPI_STRIDE + mq * 4]);
        *reinterpret_cast<uint4*>(
            &g_ctfT[(size_t)(n0 + col) * MTOT + m0 + mq * 4]) = v;
    }
}

// ---------------------------------------------------------------------------
// GEMM2: hebb[i,j] = sum_m xT[i,m]*cT[j,m]; new_w = plastic + pf/M*hebb; sumsq
// ---------------------------------------------------------------------------
__global__ __launch_bounds__(512, 1)
void gemm2_mma(const float* __restrict__ plastic,
               const float* __restrict__ prate,
               const float* __restrict__ hstr,
               float* __restrict__ Wout) {
    extern __shared__ uint32_t sh[];
    const uint32_t shb = (uint32_t)__cvta_generic_to_shared(sh);

    const int tid = threadIdx.x;
    const int wid = tid >> 5;
    const int lid = tid & 31;
    const int wm = wid & 3;
    const int wn = wid >> 2;
    const int r = lid >> 2;
    const int cq = lid & 3;
    const int i0 = blockIdx.y * MT;
    const int j0 = blockIdx.x * NT;

    float acc[2][8][4];
    #pragma unroll
    for (int i = 0; i < 2; i++)
        #pragma unroll
        for (int t = 0; t < 8; t++)
            #pragma unroll
            for (int q = 0; q < 4; q++) acc[i][t][q] = 0.0f;

    gemm_mainloop(g_xtfT, g_ctfT, MTOT, i0, j0, shb, acc);

    const float pf = __ldg(&prate[0]) * __ldg(&hstr[0]) * (1.0f / (float)MTOT);
    float ss = 0.0f;
    #pragma unroll
    for (int i = 0; i < 2; i++) {
        int row = i0 + wm * 32 + 16 * i + r;
        #pragma unroll
        for (int t = 0; t < 8; t++) {
            int col = j0 + wn * 64 + 8 * t + 2 * cq;
            size_t b0 = (size_t)row * HDIM + col;
            size_t b1 = (size_t)(row + 8) * HDIM + col;
            float2 p0 = *reinterpret_cast<const float2*>(&plastic[b0]);
            float2 p1 = *reinterpret_cast<const float2*>(&plastic[b1]);
            float2 o0, o1;
            o0.x = p0.x + pf * acc[i][t][0]; o0.y = p0.y + pf * acc[i][t][1];
            o1.x = p1.x + pf * acc[i][t][2]; o1.y = p1.y + pf * acc[i][t][3];
            *reinterpret_cast<float2*>(&Wout[b0]) = o0;
            *reinterpret_cast<float2*>(&Wout[b1]) = o1;
            ss += o0.x * o0.x + o0.y * o0.y + o1.x * o1.x + o1.y * o1.y;
        }
    }
    #pragma unroll
    for (int s = 16; s > 0; s >>= 1)
        ss += __shfl_xor_sync(0xFFFFFFFFu, ss, s);
    if (lid == 0) atomicAdd(&g_sumsq, ss);
}

// ---------------------------------------------------------------------------
// Launch
// ---------------------------------------------------------------------------
extern "C" void kernel_launch(void* const* d_in, const int* in_sizes, int n_in,
                              void* d_out, int out_size) {
    const float* x       = (const float*)d_in[0];
    const float* plastic = (const float*)d_in[1];
    const float* prate   = (const float*)d_in[2];
    const float* fixed_w = (const float*)d_in[3];
    const float* fixed_b = (const float*)d_in[4];
    const float* hstr    = (const float*)d_in[5];

    float* combined = (float*)d_out;
    float* new_w    = (float*)d_out + COMBINED_ELEMS;

    static bool attr_done = false;
    if (!attr_done) {
        cudaFuncSetAttribute(gemm1_mma,
            cudaFuncAttributeMaxDynamicSharedMemorySize, G_SMEM_BYTES);
        cudaFuncSetAttribute(gemm2_mma,
            cudaFuncAttributeMaxDynamicSharedMemorySize, G_SMEM_BYTES);
        attr_done = true;
    }

    wsumtf_kernel<<<W_ELEMS / 4 / 256, 256>>>(fixed_w, plastic);
    xcvt_kernel<<<dim3(HDIM / 32, MTOT / 32), dim3(32, 8)>>>(x);

    gemm1_mma<<<dim3(HDIM / NT, MTOT / MT), 512, G_SMEM_BYTES>>>(
        fixed_b, combined);

    gemm2_mma<<<dim3(HDIM / NT, HDIM / MT), 512, G_SMEM_BYTES>>>(
        plastic, prate, hstr, new_w);

    scale_w_kernel<<<W_ELEMS / 4 / 256, 256>>>(new_w);
}

// round 14
// speedup vs baseline: 1.3446x; 1.3446x over previous
#include <cuda_runtime.h>
#include <cstdint>

#define HDIM 2048
#define MTOT 16384
#define COMBINED_ELEMS (MTOT * HDIM)
#define W_ELEMS (HDIM * HDIM)

// Scratch (static __device__ — no allocation allowed)
__device__ __align__(256) uint32_t g_xtf[MTOT * HDIM];    // x tf32, [m][h]
__device__ __align__(256) uint32_t g_xtfT[HDIM * MTOT];   // x tf32, [h][m]
__device__ __align__(256) uint32_t g_wtf[W_ELEMS];        // fixed+plastic tf32, [n][k]
__device__ __align__(256) float    g_G[W_ELEMS];          // G = x^T x, fp32
__device__ __align__(256) float    g_sx[HDIM];            // column sums of x
__device__ float g_sumsq;

// ---------------------------------------------------------------------------
// Helpers (baseline sm_80+ ISA only)
// ---------------------------------------------------------------------------
__device__ __forceinline__ uint32_t f2tf32(float f) {
    uint32_t r;
    asm("cvt.rna.tf32.f32 %0, %1;" : "=r"(r) : "f"(f));
    return r;
}

__device__ __forceinline__ void mma_tf32(float* d, const uint32_t* a, const uint32_t* b) {
    asm volatile(
        "mma.sync.aligned.m16n8k8.row.col.f32.tf32.tf32.f32 "
        "{%0,%1,%2,%3}, {%4,%5,%6,%7}, {%8,%9}, {%0,%1,%2,%3};"
        : "+f"(d[0]), "+f"(d[1]), "+f"(d[2]), "+f"(d[3])
        : "r"(a[0]), "r"(a[1]), "r"(a[2]), "r"(a[3]), "r"(b[0]), "r"(b[1]));
}

#define LDSM_X4(d, addr) \
    asm volatile("ldmatrix.sync.aligned.m8n8.x4.shared.b16 {%0,%1,%2,%3}, [%4];" \
        : "=r"((d)[0]), "=r"((d)[1]), "=r"((d)[2]), "=r"((d)[3]) : "r"(addr))

__device__ __forceinline__ void cp16(uint32_t smem_addr, const void* gptr) {
    asm volatile("cp.async.cg.shared.global [%0], [%1], 16;"
                 :: "r"(smem_addr), "l"(gptr) : "memory");
}
__device__ __forceinline__ void cp_commit() {
    asm volatile("cp.async.commit_group;" ::: "memory");
}
__device__ __forceinline__ void cp_wait1() {
    asm volatile("cp.async.wait_group 1;" ::: "memory");
}
__device__ __forceinline__ void cp_wait0() {
    asm volatile("cp.async.wait_group 0;" ::: "memory");
}
__device__ __forceinline__ void red_add(float* gaddr, float v) {
    asm volatile("red.global.add.f32 [%0], %1;" :: "l"(gaddr), "f"(v) : "memory");
}

// ---------------------------------------------------------------------------
// Small kernels
// ---------------------------------------------------------------------------
// Prologue: g_wtf = tf32(fixed+plastic); zero g_G, g_sx, g_sumsq
__global__ void prologue_kernel(const float* __restrict__ fw,
                                const float* __restrict__ pw) {
    int gid = blockIdx.x * blockDim.x + threadIdx.x;
    if (gid == 0) g_sumsq = 0.0f;
    if (gid < HDIM) g_sx[gid] = 0.0f;
    int i = gid * 4;
    float4 a = *reinterpret_cast<const float4*>(&fw[i]);
    float4 b = *reinterpret_cast<const float4*>(&pw[i]);
    *reinterpret_cast<uint4*>(&g_wtf[i]) =
        make_uint4(f2tf32(a.x + b.x), f2tf32(a.y + b.y),
                   f2tf32(a.z + b.z), f2tf32(a.w + b.w));
    *reinterpret_cast<float4*>(&g_G[i]) = make_float4(0.f, 0.f, 0.f, 0.f);
}

// Fused: read x once -> g_xtf [m][h], g_xtfT [h][m], and column sums g_sx
__global__ void xcvt_kernel(const float* __restrict__ X) {
    __shared__ uint32_t t[32][33];
    __shared__ float s_sx[8][32];
    int bx = blockIdx.x * 32;   // h
    int by = blockIdx.y * 32;   // m
    int tx = threadIdx.x, ty = threadIdx.y;
    float part = 0.0f;
    #pragma unroll
    for (int j = 0; j < 32; j += 8) {
        float f = X[(size_t)(by + ty + j) * HDIM + bx + tx];
        part += f;
        uint32_t v = f2tf32(f);
        t[ty + j][tx] = v;
        g_xtf[(size_t)(by + ty + j) * HDIM + bx + tx] = v;
    }
    s_sx[ty][tx] = part;
    __syncthreads();
    #pragma unroll
    for (int j = 0; j < 32; j += 8)
        g_xtfT[(size_t)(bx + ty + j) * MTOT + by + tx] = t[tx][ty + j];
    if (ty == 0) {
        float s = 0.0f;
        #pragma unroll
        for (int j = 0; j < 8; j++) s += s_sx[j][tx];
        atomicAdd(&g_sx[bx + tx], s);
    }
}

__global__ void scale_w_kernel(float* __restrict__ W) {
    float n = sqrtf(g_sumsq);
    float s = (n > 1.0f) ? (1.0f / n) : 1.0f;
    int i = (blockIdx.x * blockDim.x + threadIdx.x) * 4;
    float4 v = *reinterpret_cast<float4*>(&W[i]);
    v.x *= s; v.y *= s; v.z *= s; v.w *= s;
    *reinterpret_cast<float4*>(&W[i]) = v;
}

// ---------------------------------------------------------------------------
// Proven R9 GEMM mainloop: NT 128x128 tile, 256 thr, KCH=32, 3-stage cp.async,
// LDSM fragments. SMEM [row][k], stride 36 u32. 8 warps = 4(m) x 2(n).
// Generalized with lda/ldb/Klen (pointers pre-offset for K-splits).
// ---------------------------------------------------------------------------
#define KCH 32
#define S1 36
#define G_MAT (128 * S1)
#define G_STAGE (2 * G_MAT)
#define G_SMEM_BYTES (3 * G_STAGE * 4)    // 110592 B
#define EPI_STRIDE 132

__device__ __forceinline__ void gemm_mainloop(
    const uint32_t* Aq, const uint32_t* Bq,
    int lda, int ldb, int Klen, int r0g, int c0g,
    uint32_t shb, float acc[2][8][4])
{
    const int tid = threadIdx.x;
    const int lid = tid & 31;
    const int wid = tid >> 5;
    const int wm = wid & 3;
    const int wn = wid >> 2;
    const int nchunk = Klen / KCH;

    const uint32_t aoff0 =
        (uint32_t)((wm * 32 + ((lid >> 3) & 1) * 8 + (lid & 7)) * S1
                   + ((lid >> 4) & 1) * 4) * 4;
    const uint32_t aoff1 = aoff0 + 16 * S1 * 4;
    const uint32_t boff0 =
        (uint32_t)((wn * 64 + ((lid >> 4) & 1) * 8 + (lid & 7)) * S1
                   + ((lid >> 3) & 1) * 4) * 4;

    const int srow = tid >> 3;
    const int skq  = tid & 7;

    auto issue = [&](int c) {
        const int s = c % 3;
        const uint32_t sa = shb + (uint32_t)(s * G_STAGE) * 4;
        const uint32_t sb = sa + (uint32_t)G_MAT * 4;
        const int k0 = c * KCH;
        #pragma unroll
        for (int i = 0; i < 4; i++) {
            int row = srow + i * 32;
            cp16(sa + (uint32_t)(row * S1 + skq * 4) * 4,
                 &Aq[(size_t)(r0g + row) * lda + k0 + skq * 4]);
            cp16(sb + (uint32_t)(row * S1 + skq * 4) * 4,
                 &Bq[(size_t)(c0g + row) * ldb + k0 + skq * 4]);
        }
        cp_commit();
    };

    issue(0);
    issue(1);

    for (int c = 0; c < nchunk; c++) {
        if (c >= nchunk - 2) cp_wait0(); else cp_wait1();
        __syncthreads();
        if (c + 2 < nchunk) issue(c + 2);

        const uint32_t sa = shb + (uint32_t)((c % 3) * G_STAGE) * 4;
        const uint32_t sb = sa + (uint32_t)G_MAT * 4;

        uint32_t afr[2][8];
        uint32_t bfr[2][4];
        LDSM_X4(&afr[0][0], sa + aoff0);
        LDSM_X4(&afr[0][4], sa + aoff1);
        LDSM_X4(bfr[0], sb + boff0);

        #pragma unroll
        for (int ks = 0; ks < 4; ks++) {
            const int ap = ks & 1;
            #pragma unroll
            for (int tp = 0; tp < 4; tp++) {
                if (tp < 3) {
                    LDSM_X4(bfr[(tp + 1) & 1],
                            sb + boff0 + (uint32_t)((tp + 1) * 16 * S1 * 4) + ks * 32);
                } else if (ks < 3) {
                    LDSM_X4(&afr[ap ^ 1][0], sa + aoff0 + (ks + 1) * 32);
                    LDSM_X4(&afr[ap ^ 1][4], sa + aoff1 + (ks + 1) * 32);
                    LDSM_X4(bfr[0], sb + boff0 + (ks + 1) * 32);
                }
                const uint32_t* bb = bfr[tp & 1];
                mma_tf32(acc[0][2 * tp],     &afr[ap][0], &bb[0]);
                mma_tf32(acc[1][2 * tp],     &afr[ap][4], &bb[0]);
                mma_tf32(acc[0][2 * tp + 1], &afr[ap][0], &bb[2]);
                mma_tf32(acc[1][2 * tp + 1], &afr[ap][4], &bb[2]);
            }
        }
    }
    __syncthreads();
}

// ---------------------------------------------------------------------------
// GEMM1: combined[m,n] = sum_k x[m,k]*wsum[n,k] + bias[n]
// ---------------------------------------------------------------------------
__global__ __launch_bounds__(256, 2)
void gemm1_mma(const float* __restrict__ bias,
               float* __restrict__ C) {
    extern __shared__ uint32_t sh[];
    const uint32_t shb = (uint32_t)__cvta_generic_to_shared(sh);

    const int tid = threadIdx.x;
    const int wid = tid >> 5;
    const int lid = tid & 31;
    const int wm = wid & 3;
    const int wn = wid >> 2;
    const int r = lid >> 2;
    const int cq = lid & 3;
    const int m0 = blockIdx.y * 128;
    const int n0 = blockIdx.x * 128;

    float acc[2][8][4];
    #pragma unroll
    for (int i = 0; i < 2; i++)
        #pragma unroll
        for (int t = 0; t < 8; t++)
            #pragma unroll
            for (int q = 0; q < 4; q++) acc[i][t][q] = 0.0f;

    gemm_mainloop(g_xtf, g_wtf, HDIM, HDIM, HDIM, m0, n0, shb, acc);

    #pragma unroll
    for (int i = 0; i < 2; i++) {
        int row = m0 + wm * 32 + 16 * i + r;
        #pragma unroll
        for (int t = 0; t < 8; t++) {
            int col = n0 + wn * 64 + 8 * t + 2 * cq;
            float2 bv = *reinterpret_cast<const float2*>(&bias[col]);
            size_t b0 = (size_t)row * HDIM + col;
            size_t b1 = (size_t)(row + 8) * HDIM + col;
            *reinterpret_cast<float2*>(&C[b0]) =
                make_float2(acc[i][t][0] + bv.x, acc[i][t][1] + bv.y);
            *reinterpret_cast<float2*>(&C[b1]) =
                make_float2(acc[i][t][2] + bv.x, acc[i][t][3] + bv.y);
        }
    }
}

// ---------------------------------------------------------------------------
// XTX: G = x^T x (symmetric). 136 upper-tri 128x128 tiles x 2 K-splits.
// Accumulate into g_G (fp32) via red.add. Off-diagonal tiles mirrored via
// smem-staged transpose.
// ---------------------------------------------------------------------------
__global__ __launch_bounds__(256, 2)
void xtx_mma() {
    extern __shared__ uint32_t sh[];
    const uint32_t shb = (uint32_t)__cvta_generic_to_shared(sh);

    const int tid = threadIdx.x;
    const int wid = tid >> 5;
    const int lid = tid & 31;
    const int wm = wid & 3;
    const int wn = wid >> 2;
    const int r = lid >> 2;
    const int cq = lid & 3;

    // decode block -> (split, bi<=bj)
    const int split = blockIdx.x & 1;
    int rem = blockIdx.x >> 1;   // 0..135
    int bi = 0;
    #pragma unroll 1
    while (rem >= 16 - bi) { rem -= 16 - bi; bi++; }
    const int bj = bi + rem;
    const int i0 = bi * 128;
    const int j0 = bj * 128;

    float acc[2][8][4];
    #pragma unroll
    for (int i = 0; i < 2; i++)
        #pragma unroll
        for (int t = 0; t < 8; t++)
            #pragma unroll
            for (int q = 0; q < 4; q++) acc[i][t][q] = 0.0f;

    const uint32_t* base = g_xtfT + split * (MTOT / 2);
    gemm_mainloop(base, base, MTOT, MTOT, MTOT / 2, i0, j0, shb, acc);

    // direct RED into G[i0+..][j0+..]
    #pragma unroll
    for (int i = 0; i < 2; i++) {
        int row = i0 + wm * 32 + 16 * i + r;
        #pragma unroll
        for (int t = 0; t < 8; t++) {
            int col = j0 + wn * 64 + 8 * t + 2 * cq;
            red_add(&g_G[(size_t)row * HDIM + col],     acc[i][t][0]);
            red_add(&g_G[(size_t)row * HDIM + col + 1], acc[i][t][1]);
            red_add(&g_G[(size_t)(row + 8) * HDIM + col],     acc[i][t][2]);
            red_add(&g_G[(size_t)(row + 8) * HDIM + col + 1], acc[i][t][3]);
        }
    }

    if (bi == bj) return;

    // mirrored tile: stage transpose in smem, coalesced RED rows of G[j][i]
    float* st = reinterpret_cast<float*>(sh);
    #pragma unroll
    for (int i = 0; i < 2; i++) {
        int rl = wm * 32 + 16 * i + r;
        #pragma unroll
        for (int t = 0; t < 8; t++) {
            int cl = wn * 64 + 8 * t + 2 * cq;
            st[cl * EPI_STRIDE + rl]           = acc[i][t][0];
            st[(cl + 1) * EPI_STRIDE + rl]     = acc[i][t][1];
            st[cl * EPI_STRIDE + rl + 8]       = acc[i][t][2];
            st[(cl + 1) * EPI_STRIDE + rl + 8] = acc[i][t][3];
        }
    }
    __syncthreads();
    #pragma unroll
    for (int it = 0; it < 16; it++) {
        int slot = tid + (it << 8);
        int col = slot >> 5, mq = slot & 31;   // col 0..127, mq 0..31
        float4 v = *reinterpret_cast<const float4*>(&st[col * EPI_STRIDE + mq * 4]);
        float* gp = &g_G[(size_t)(j0 + col) * HDIM + i0 + mq * 4];
        red_add(gp + 0, v.x);
        red_add(gp + 1, v.y);
        red_add(gp + 2, v.z);
        red_add(gp + 3, v.w);
    }
}

// ---------------------------------------------------------------------------
// HEBBW: M*hebb[i,j] = sum_k G[i,k]*wsum[j,k] + sx[i]*b[j]
//        new_w = plastic + pf/M * (M*hebb);  accumulate sumsq.
// G fed as raw fp32 bits (HW uses top 19 bits as tf32).
// ---------------------------------------------------------------------------
__global__ __launch_bounds__(256, 2)
void hebbw_mma(const float* __restrict__ plastic,
               const float* __restrict__ prate,
               const float* __restrict__ hstr,
               const float* __restrict__ bias,
               float* __restrict__ Wout) {
    extern __shared__ uint32_t sh[];
    const uint32_t shb = (uint32_t)__cvta_generic_to_shared(sh);

    const int tid = threadIdx.x;
    const int wid = tid >> 5;
    const int lid = tid & 31;
    const int wm = wid & 3;
    const int wn = wid >> 2;
    const int r = lid >> 2;
    const int cq = lid & 3;
    const int i0 = blockIdx.y * 128;
    const int j0 = blockIdx.x * 128;

    float acc[2][8][4];
    #pragma unroll
    for (int i = 0; i < 2; i++)
        #pragma unroll
        for (int t = 0; t < 8; t++)
            #pragma unroll
            for (int q = 0; q < 4; q++) acc[i][t][q] = 0.0f;

    gemm_mainloop(reinterpret_cast<const uint32_t*>(g_G), g_wtf,
                  HDIM, HDIM, HDIM, i0, j0, shb, acc);

    const float pf = __ldg(&prate[0]) * __ldg(&hstr[0]) * (1.0f / (float)MTOT);
    float ss = 0.0f;
    #pragma unroll
    for (int i = 0; i < 2; i++) {
        int row = i0 + wm * 32 + 16 * i + r;
        float sx0 = g_sx[row], sx1 = g_sx[row + 8];
        #pragma unroll
        for (int t = 0; t < 8; t++) {
            int col = j0 + wn * 64 + 8 * t + 2 * cq;
            float2 bv = *reinterpret_cast<const float2*>(&bias[col]);
            size_t b0 = (size_t)row * HDIM + col;
            size_t b1 = (size_t)(row + 8) * HDIM + col;
            float2 p0 = *reinterpret_cast<const float2*>(&plastic[b0]);
            float2 p1 = *reinterpret_cast<const float2*>(&plastic[b1]);
            float2 o0, o1;
            o0.x = p0.x + pf * (acc[i][t][0] + sx0 * bv.x);
            o0.y = p0.y + pf * (acc[i][t][1] + sx0 * bv.y);
            o1.x = p1.x + pf * (acc[i][t][2] + sx1 * bv.x);
            o1.y = p1.y + pf * (acc[i][t][3] + sx1 * bv.y);
            *reinterpret_cast<float2*>(&Wout[b0]) = o0;
            *reinterpret_cast<float2*>(&Wout[b1]) = o1;
            ss += o0.x * o0.x + o0.y * o0.y + o1.x * o1.x + o1.y * o1.y;
        }
    }
    #pragma unroll
    for (int s = 16; s > 0; s >>= 1)
        ss += __shfl_xor_sync(0xFFFFFFFFu, ss, s);
    if (lid == 0) atomicAdd(&g_sumsq, ss);
}

// ---------------------------------------------------------------------------
// Launch
// ---------------------------------------------------------------------------
extern "C" void kernel_launch(void* const* d_in, const int* in_sizes, int n_in,
                              void* d_out, int out_size) {
    const float* x       = (const float*)d_in[0];
    const float* plastic = (const float*)d_in[1];
    const float* prate   = (const float*)d_in[2];
    const float* fixed_w = (const float*)d_in[3];
    const float* fixed_b = (const float*)d_in[4];
    const float* hstr    = (const float*)d_in[5];

    float* combined = (float*)d_out;
    float* new_w    = (float*)d_out + COMBINED_ELEMS;

    static bool attr_done = false;
    if (!attr_done) {
        cudaFuncSetAttribute(gemm1_mma,
            cudaFuncAttributeMaxDynamicSharedMemorySize, G_SMEM_BYTES);
        cudaFuncSetAttribute(xtx_mma,
            cudaFuncAttributeMaxDynamicSharedMemorySize, G_SMEM_BYTES);
        cudaFuncSetAttribute(hebbw_mma,
            cudaFuncAttributeMaxDynamicSharedMemorySize, G_SMEM_BYTES);
        attr_done = true;
    }

    prologue_kernel<<<W_ELEMS / 4 / 256, 256>>>(fixed_w, plastic);
    xcvt_kernel<<<dim3(HDIM / 32, MTOT / 32), dim3(32, 8)>>>(x);

    // G = x^T x  (symmetric, 136 upper-tri tiles x 2 K-splits)
    xtx_mma<<<272, 256, G_SMEM_BYTES>>>();

    // combined = x @ wsum^T + b
    gemm1_mma<<<dim3(HDIM / 128, MTOT / 128), 256, G_SMEM_BYTES>>>(
        fixed_b, combined);

    // new_w from G @ wsum^T + sx (x) b
    hebbw_mma<<<dim3(HDIM / 128, HDIM / 128), 256, G_SMEM_BYTES>>>(
        plastic, prate, hstr, fixed_b, new_w);

    scale_w_kernel<<<W_ELEMS / 4 / 256, 256>>>(new_w);
}